// round 1
// baseline (speedup 1.0000x reference)
#include <cuda_runtime.h>
#include <cstddef>

#define B_   2
#define N_   768
#define BN_  1536            // B_*N_
#define D_   512
#define E_   64
#define LN_EPS 1e-5f

// ---------------- scratch (static device allocations; allowed) ----------------
__device__ float g_WR[D_ * E_];          // fused W_edges@W_rows, stored [d][f]
__device__ float g_WC[D_ * E_];          // fused W_edges@W_cols, stored [d][f]
__device__ float g_pR[4 * BN_ * E_];     // partial row-GEMM accumulators (4 d-parts)
__device__ float g_pC[4 * BN_ * E_];
__device__ float g_Rc[BN_ * E_];         // centered R' = R - mean(R)
__device__ float g_Cc[BN_ * E_];         // centered C'
__device__ float g_varR[BN_];
__device__ float g_varC[BN_];

// ---------------- kernel A: WR[d][f] = sum_e W_edges[f][e] * W_rows[e][d] ----
// grid 128, block 256; idx = f*512 + d so W_rows/W_cols reads are coalesced,
// W_edges read is a warp-uniform broadcast.
__global__ void kA(const float* __restrict__ We,
                   const float* __restrict__ Wr,
                   const float* __restrict__ Wc) {
    int idx = blockIdx.x * 256 + threadIdx.x;   // 0 .. 32767
    int f = idx >> 9;
    int d = idx & 511;
    float ar = 0.f, ac = 0.f;
#pragma unroll 8
    for (int e = 0; e < E_; e++) {
        float we = We[f * E_ + e];
        ar = fmaf(we, Wr[e * D_ + d], ar);
        ac = fmaf(we, Wc[e * D_ + d], ac);
    }
    g_WR[d * E_ + f] = ar;
    g_WC[d * E_ + f] = ac;
}

// ---------------- kernel B: partial row GEMM ---------------------------------
// grid (96 row-tiles, 4 d-parts), block 256. Each block: 16 rows x 128 d-slice.
// Thread layout: f = tid&63, group g = tid>>6 handles 4 rows.
__global__ void kB(const float* __restrict__ x) {
    __shared__ float xs[16 * 128];
    int row0 = blockIdx.x * 16;
    int d0   = blockIdx.y * 128;
    int tid  = threadIdx.x;

    for (int idx = tid; idx < 16 * 128; idx += 256) {
        int r  = idx >> 7;
        int dd = idx & 127;
        xs[idx] = x[(row0 + r) * D_ + d0 + dd];
    }
    __syncthreads();

    int f = tid & 63;
    int g = tid >> 6;
    float aR[4] = {0.f, 0.f, 0.f, 0.f};
    float aC[4] = {0.f, 0.f, 0.f, 0.f};
    const float* wrp = g_WR + d0 * E_ + f;
    const float* wcp = g_WC + d0 * E_ + f;
    const float* xp  = xs + (g * 4) * 128;

#pragma unroll 4
    for (int dd = 0; dd < 128; dd++) {
        float wr = wrp[dd * E_];
        float wc = wcp[dd * E_];
#pragma unroll
        for (int k = 0; k < 4; k++) {
            float xv = xp[k * 128 + dd];
            aR[k] = fmaf(xv, wr, aR[k]);
            aC[k] = fmaf(xv, wc, aC[k]);
        }
    }
#pragma unroll
    for (int k = 0; k < 4; k++) {
        int row = row0 + g * 4 + k;
        g_pR[(blockIdx.y * BN_ + row) * E_ + f] = aR[k];
        g_pC[(blockIdx.y * BN_ + row) * E_ + f] = aC[k];
    }
}

// ---------------- kernel B2: reduce partials + center + variance -------------
// grid 1536, block 64 (one row per block, one f per thread).
__global__ void kB2() {
    int row = blockIdx.x;
    int f   = threadIdx.x;
    float rv = 0.f, cv = 0.f;
#pragma unroll
    for (int p = 0; p < 4; p++) {
        rv += g_pR[(p * BN_ + row) * E_ + f];
        cv += g_pC[(p * BN_ + row) * E_ + f];
    }
    float s0 = rv, s1 = rv * rv, s2 = cv, s3 = cv * cv;
#pragma unroll
    for (int o = 16; o; o >>= 1) {
        s0 += __shfl_xor_sync(0xffffffffu, s0, o);
        s1 += __shfl_xor_sync(0xffffffffu, s1, o);
        s2 += __shfl_xor_sync(0xffffffffu, s2, o);
        s3 += __shfl_xor_sync(0xffffffffu, s3, o);
    }
    __shared__ float sm[2][4];
    int w = f >> 5;
    if ((f & 31) == 0) { sm[w][0] = s0; sm[w][1] = s1; sm[w][2] = s2; sm[w][3] = s3; }
    __syncthreads();
    float sR  = sm[0][0] + sm[1][0];
    float sRR = sm[0][1] + sm[1][1];
    float sC  = sm[0][2] + sm[1][2];
    float sCC = sm[0][3] + sm[1][3];
    float mR = sR * (1.f / 64.f);
    float mC = sC * (1.f / 64.f);
    g_Rc[row * E_ + f] = rv - mR;
    g_Cc[row * E_ + f] = cv - mC;
    if (f == 0) {
        g_varR[row] = sRR * (1.f / 64.f) - mR * mR;
        g_varC[row] = sCC * (1.f / 64.f) - mC * mC;
    }
}

// ---------------- kernel C: the store-bound epilogue --------------------------
// grid (48 i-tiles, 48 j-tiles, 2 batches), block 256 (8 warps).
// Each block: 16x16 (i,j) pairs; warp w handles ii in {2w,2w+1}, all 16 jj.
// Per pair: one 64-wide dot (5 bfly shfls), rsqrt, 256B float2 store.
__global__ void __launch_bounds__(256) kC(const float* __restrict__ gamma,
                                          const float* __restrict__ beta,
                                          float* __restrict__ out) {
    __shared__ float rs[16 * E_];
    __shared__ float cs[16 * E_];
    __shared__ float vR[16];
    __shared__ float vC[16];

    int i0 = blockIdx.x * 16;
    int j0 = blockIdx.y * 16;
    int b  = blockIdx.z;
    int tid = threadIdx.x;
    int rowRbase = b * N_ + i0;
    int rowCbase = b * N_ + j0;

    for (int idx = tid; idx < 16 * E_; idx += 256) {
        rs[idx] = g_Rc[rowRbase * E_ + idx];
        cs[idx] = g_Cc[rowCbase * E_ + idx];
    }
    if (tid < 16)       vR[tid]      = g_varR[rowRbase + tid];
    else if (tid < 32)  vC[tid - 16] = g_varC[rowCbase + tid - 16];

    int lane = tid & 31;
    int w    = tid >> 5;
    float2 gm = ((const float2*)gamma)[lane];
    float2 bt = ((const float2*)beta)[lane];
    __syncthreads();

    const float2* rs2 = (const float2*)rs;
    const float2* cs2 = (const float2*)cs;
    float2* out2 = (float2*)out;

#pragma unroll
    for (int kk = 0; kk < 2; kk++) {
        int ii = 2 * w + kk;
        float2 r = rs2[ii * 32 + lane];
        float vr = vR[ii];
        size_t ob = ((size_t)(b * N_ + i0 + ii) * N_ + j0) * 32 + lane;  // float2 units
#pragma unroll
        for (int jj = 0; jj < 16; jj++) {
            float2 c = cs2[jj * 32 + lane];
            float d = fmaf(r.x, c.x, r.y * c.y);
            d += __shfl_xor_sync(0xffffffffu, d, 16);
            d += __shfl_xor_sync(0xffffffffu, d, 8);
            d += __shfl_xor_sync(0xffffffffu, d, 4);
            d += __shfl_xor_sync(0xffffffffu, d, 2);
            d += __shfl_xor_sync(0xffffffffu, d, 1);
            float var = vr + vC[jj] + d * (2.0f / 64.0f);
            float inv = rsqrtf(var + LN_EPS);
            float2 o;
            o.x = fmaf((r.x + c.x) * inv, gm.x, bt.x);
            o.y = fmaf((r.y + c.y) * inv, gm.y, bt.y);
            out2[ob + (size_t)jj * 32] = o;
        }
    }
}

// ---------------- launch -------------------------------------------------------
extern "C" void kernel_launch(void* const* d_in, const int* in_sizes, int n_in,
                              void* d_out, int out_size) {
    const float* x     = (const float*)d_in[0];  // [2,768,512]
    const float* Wr    = (const float*)d_in[1];  // [64,512]
    const float* Wc    = (const float*)d_in[2];  // [64,512]
    const float* We    = (const float*)d_in[3];  // [64,64]
    const float* gamma = (const float*)d_in[4];  // [64]
    const float* beta  = (const float*)d_in[5];  // [64]
    float* out = (float*)d_out;                  // [2,768,768,64] fp32

    kA<<<128, 256>>>(We, Wr, Wc);
    kB<<<dim3(BN_ / 16, 4), 256>>>(x);
    kB2<<<BN_, 64>>>();
    kC<<<dim3(N_ / 16, N_ / 16, B_), 256>>>(gamma, beta, out);
}